// round 13
// baseline (speedup 1.0000x reference)
#include <cuda_runtime.h>

#define HH 96
#define WW 96
#define NPIX 9216
#define NHEADS 8
#define HD 16
#define HSUB 48
#define NKEY (HSUB*HSUB)
#define NCTA 288u

typedef unsigned long long u64;

// Planar scratch layouts (coalesced: plane-major, pixel-minor).
__device__ __align__(16) float4 g_q4[NHEADS * 4 * NPIX];
__device__ __align__(16) float4 g_k4[NHEADS * 4 * NKEY];
__device__ __align__(16) float4 g_v4[NHEADS * 4 * NKEY];
__device__ __align__(16) float4 g_att4[32 * NPIX];

// Device-wide barrier state (zero-initialized; self-resetting per replay).
__device__ volatile unsigned g_barA[2];
__device__ volatile unsigned g_barB[2];

// ---- f32x2 packed math helpers -------------------------------------------
__device__ __forceinline__ u64 pk2(float lo, float hi) {
    u64 r; asm("mov.b64 %0,{%1,%2};" : "=l"(r) : "f"(lo), "f"(hi)); return r;
}
__device__ __forceinline__ void upk2(u64 p, float& lo, float& hi) {
    asm("mov.b64 {%0,%1},%2;" : "=f"(lo), "=f"(hi) : "l"(p));
}
__device__ __forceinline__ u64 ffma2(u64 a, u64 b, u64 c) {
    u64 d; asm("fma.rn.f32x2 %0,%1,%2,%3;" : "=l"(d) : "l"(a), "l"(b), "l"(c)); return d;
}
__device__ __forceinline__ u64 fmul2(u64 a, u64 b) {
    u64 d; asm("mul.rn.f32x2 %0,%1,%2;" : "=l"(d) : "l"(a), "l"(b)); return d;
}

// ---- device-wide barrier (all 288 CTAs guaranteed resident) ---------------
__device__ __forceinline__ void global_barrier(int id) {
    __syncthreads();
    if (threadIdx.x == 0) {
        __threadfence();
        atomicAdd((unsigned*)&g_barA[id], 1u);
        while (g_barA[id] < NCTA) __nanosleep(64);
        __threadfence();
        unsigned b = atomicAdd((unsigned*)&g_barB[id], 1u) + 1u;
        if (b == NCTA) {              // last acker resets for next replay;
            g_barA[id] = 0u;          // everyone has already passed the spin.
            __threadfence();
            g_barB[id] = 0u;
        }
    }
    __syncthreads();
}

// Shared-memory overlay: attn tiles / proj tiles / conv weights. 48KB.
union __align__(16) SmemU {
    struct { u64 Kt[2560]; u64 Vt[2560]; } a;          // 40960 B
    struct { float As[64 * 64]; float Bs[64 * 128]; } p;  // 49152 B
    struct { float ws[36]; float bs[4]; } c;           // 160 B
};

// ---------------------------------------------------------------------------
// Conv unit (identical math to round-12 conv kernel; unit b in [0,1152)).
// ---------------------------------------------------------------------------
__device__ __forceinline__ void conv_unit(int b, int tid,
        const float* __restrict__ x, const float* __restrict__ wq,
        const float* __restrict__ bq, float* ws, float* bs) {
    int o0;
    if (b < 576) o0 = (b / 18) * 4;
    else {
        int b2 = b - 576;
        const bool isk = b2 < 288;
        if (!isk) b2 -= 288;
        o0 = (isk ? 128 : 256) + (b2 / 9) * 4;
    }
    __syncthreads();                     // protect previous unit's ws/bs use
    if (tid < 36) ws[tid] = wq[o0 * 9 + tid];
    if (tid < 4)  bs[tid] = bq[o0 + tid];
    __syncthreads();

    const int s   = 3 - (o0 % 3);
    const int ic0 = o0 / 3;

    if (b < 576) {
        // q path: vertical pair of output quads
        const int plane = b / 18;
        const int idx = (b - plane * 18) * 256 + tid;
        const int pi = idx / 96, j = idx - pi * 96;
        const int i0 = 2 * pi;
        const bool up = i0 > 0, dn = i0 < 94, lf = j > 0, rt = j < 95;
        const int base = i0 * 96 + j;

        float a0A[4], a0B[4], a1A[4], a1B[4];
        #pragma unroll
        for (int pass = 0; pass < 2; pass++) {
            const float* xp = x + (size_t)(ic0 + pass) * NPIX + base;
            float m0 = (up && lf) ? xp[-97] : 0.f;
            float m1 = up         ? xp[-96] : 0.f;
            float m2 = (up && rt) ? xp[-95] : 0.f;
            float r00 = lf ? xp[-1] : 0.f;
            float r01 =      xp[0];
            float r02 = rt ? xp[1]  : 0.f;
            float r10 = lf ? xp[95] : 0.f;
            float r11 =      xp[96];
            float r12 = rt ? xp[97] : 0.f;
            float r20 = (dn && lf) ? xp[191] : 0.f;
            float r21 = dn         ? xp[192] : 0.f;
            float r22 = (dn && rt) ? xp[193] : 0.f;
            float* acc0 = pass ? a0B : a0A;
            float* acc1 = pass ? a1B : a1A;
            #pragma unroll
            for (int e = 0; e < 4; e++) {
                const float* w = ws + e * 9;
                float a = bs[e], c = bs[e];
                a = fmaf(w[0], m0, a);  a = fmaf(w[1], m1, a);  a = fmaf(w[2], m2, a);
                a = fmaf(w[3], r00, a); a = fmaf(w[4], r01, a); a = fmaf(w[5], r02, a);
                a = fmaf(w[6], r10, a); a = fmaf(w[7], r11, a); a = fmaf(w[8], r12, a);
                c = fmaf(w[0], r00, c); c = fmaf(w[1], r01, c); c = fmaf(w[2], r02, c);
                c = fmaf(w[3], r10, c); c = fmaf(w[4], r11, c); c = fmaf(w[5], r12, c);
                c = fmaf(w[6], r20, c); c = fmaf(w[7], r21, c); c = fmaf(w[8], r22, c);
                acc0[e] = a;
                acc1[e] = c;
            }
        }
        float o0v[4], o1v[4];
        #pragma unroll
        for (int e = 0; e < 4; e++) {
            o0v[e] = ((e < s) ? a0A[e] : a0B[e]) * 0.25f;
            o1v[e] = ((e < s) ? a1A[e] : a1B[e]) * 0.25f;
        }
        float4* dst = g_q4 + (size_t)plane * NPIX + base;
        dst[0]  = make_float4(o0v[0], o0v[1], o0v[2], o0v[3]);
        dst[96] = make_float4(o1v[0], o1v[1], o1v[2], o1v[3]);
    } else {
        int b2 = b - 576;
        const bool isk = b2 < 288;
        if (!isk) b2 -= 288;
        const int plane = b2 / 9;
        const int key = (b2 - plane * 9) * 256 + tid;
        const int gr = key / 48, gc = key - gr * 48;
        const int i = gr * 2, j = gc * 2;
        const bool up = i > 0, dn = i < 95, lf = j > 0, rt = j < 95;
        const int base = i * 96 + j;

        float accA[4], accB[4];
        #pragma unroll
        for (int pass = 0; pass < 2; pass++) {
            const float* xp = x + (size_t)(ic0 + pass) * NPIX + base;
            float v0 = (up && lf) ? xp[-97] : 0.f;
            float v1 = up         ? xp[-96] : 0.f;
            float v2 = (up && rt) ? xp[-95] : 0.f;
            float v3 = lf         ? xp[-1]  : 0.f;
            float v4 =              xp[0];
            float v5 = rt         ? xp[1]   : 0.f;
            float v6 = (dn && lf) ? xp[95]  : 0.f;
            float v7 = dn         ? xp[96]  : 0.f;
            float v8 = (dn && rt) ? xp[97]  : 0.f;
            float* acc = pass ? accB : accA;
            #pragma unroll
            for (int e = 0; e < 4; e++) {
                const float* w = ws + e * 9;
                float a = bs[e];
                a = fmaf(w[0], v0, a); a = fmaf(w[1], v1, a); a = fmaf(w[2], v2, a);
                a = fmaf(w[3], v3, a); a = fmaf(w[4], v4, a); a = fmaf(w[5], v5, a);
                a = fmaf(w[6], v6, a); a = fmaf(w[7], v7, a); a = fmaf(w[8], v8, a);
                acc[e] = a;
            }
        }
        float outv[4];
        #pragma unroll
        for (int e = 0; e < 4; e++)
            outv[e] = (e < s) ? accA[e] : accB[e];
        float4* dst = (isk ? g_k4 : g_v4) + (size_t)plane * NKEY + key;
        *dst = make_float4(outv[0], outv[1], outv[2], outv[3]);
    }
}

// ---------------------------------------------------------------------------
// Fused persistent kernel: conv -> barrier -> attn -> barrier -> proj.
// ---------------------------------------------------------------------------
__global__ __launch_bounds__(256, 2) void fused_kernel(
        const float* __restrict__ x,
        const float* __restrict__ wq,
        const float* __restrict__ bq,
        const float* __restrict__ pw,
        const float* __restrict__ pb,
        float* __restrict__ out) {
    __shared__ SmemU sm;
    const int cta = blockIdx.x;
    const int tid = threadIdx.x;

    // ------------------- Phase 1: conv (4 units per CTA) -------------------
    #pragma unroll
    for (int u = 0; u < 4; u++)
        conv_unit(cta + u * 288, tid, x, wq, bq, sm.c.ws, sm.c.bs);

    global_barrier(0);

    // ------------------- Phase 2: attn (1 unit per CTA) --------------------
    {
        const int tj = cta % 6, ti = (cta / 6) % 6, n = cta / 36;

        const int si0 = min(max(ti * 8 - 3, 0), 40);
        const int sj0 = min(max(tj * 8 - 3, 0), 40);

        {
            int kr = tid >> 4, kc = tid & 15;
            int gr = min(si0 + kr, 47);
            int gc = min(sj0 + kc, 47);
            const int key = gr * HSUB + gc;
            const ulonglong2* kg = (const ulonglong2*)g_k4 + (size_t)(n * 4) * NKEY + key;
            const ulonglong2* vg = (const ulonglong2*)g_v4 + (size_t)(n * 4) * NKEY + key;
            #pragma unroll
            for (int e = 0; e < 4; e++) {
                ulonglong2 a = kg[e * NKEY];
                sm.a.Kt[tid * 10 + 2 * e]     = a.x;
                sm.a.Kt[tid * 10 + 2 * e + 1] = a.y;
                ulonglong2 b = vg[e * NKEY];
                sm.a.Vt[tid * 10 + 2 * e]     = b.x;
                sm.a.Vt[tid * 10 + 2 * e + 1] = b.y;
            }
        }
        __syncthreads();

        const int warp = tid >> 5, lane = tid & 31;
        const int qil = (warp >> 1) * 4 + (lane >> 3);
        const int qjl = (warp & 1) * 8 + (lane & 7);
        const int qi = ti * 16 + qil;
        const int qj = tj * 16 + qjl;
        const int pix = qi * 96 + qj;
        const int reli = min(max((qi >> 1) - 3, 0), 40) - si0;
        const int relj = min(max((qj >> 1) - 3, 0), 40) - sj0;

        u64 qp[8];
        {
            const ulonglong2* qg = (const ulonglong2*)g_q4 + (size_t)(n * 4) * NPIX + pix;
            #pragma unroll
            for (int e = 0; e < 4; e++) {
                ulonglong2 a = qg[e * NPIX];
                qp[2 * e] = a.x; qp[2 * e + 1] = a.y;
            }
        }

        float mx = -3.4e38f;
        float sum = 0.f;
        u64 av[8];
        #pragma unroll
        for (int e = 0; e < 8; e++) av[e] = 0ull;

        #pragma unroll
        for (int ch = 0; ch < 4; ch++) {
            float lg[16];
            float cmx = -3.4e38f;
            #pragma unroll
            for (int p = 0; p < 2; p++) {
                const int rb = (reli + ch * 2 + p) * 16 + relj;
                #pragma unroll
                for (int cc = 0; cc < 8; cc++) {
                    const ulonglong2* kp = (const ulonglong2*)&sm.a.Kt[(rb + cc) * 10];
                    ulonglong2 k0 = kp[0], k1 = kp[1], k2 = kp[2], k3 = kp[3];
                    u64 acc = fmul2(qp[0], k0.x);
                    acc = ffma2(qp[1], k0.y, acc);
                    acc = ffma2(qp[2], k1.x, acc);
                    acc = ffma2(qp[3], k1.y, acc);
                    acc = ffma2(qp[4], k2.x, acc);
                    acc = ffma2(qp[5], k2.y, acc);
                    acc = ffma2(qp[6], k3.x, acc);
                    acc = ffma2(qp[7], k3.y, acc);
                    float lo, hi; upk2(acc, lo, hi);
                    float s = lo + hi;
                    lg[p * 8 + cc] = s;
                    cmx = fmaxf(cmx, s);
                }
            }
            const float nmx = fmaxf(mx, cmx);
            const float resc = __expf(mx - nmx);
            sum *= resc;
            const u64 resc2 = pk2(resc, resc);
            #pragma unroll
            for (int e = 0; e < 8; e++) av[e] = fmul2(av[e], resc2);
            mx = nmx;

            #pragma unroll
            for (int k = 0; k < 16; k++) {
                float e = __expf(lg[k] - nmx);
                lg[k] = e;
                sum += e;
            }

            #pragma unroll
            for (int p = 0; p < 2; p++) {
                const int rb = (reli + ch * 2 + p) * 16 + relj;
                #pragma unroll
                for (int cc = 0; cc < 8; cc++) {
                    const float wv = lg[p * 8 + cc];
                    const u64 w2 = pk2(wv, wv);
                    const ulonglong2* vp = (const ulonglong2*)&sm.a.Vt[(rb + cc) * 10];
                    ulonglong2 v0 = vp[0], v1 = vp[1], v2 = vp[2], v3 = vp[3];
                    av[0] = ffma2(w2, v0.x, av[0]);
                    av[1] = ffma2(w2, v0.y, av[1]);
                    av[2] = ffma2(w2, v1.x, av[2]);
                    av[3] = ffma2(w2, v1.y, av[3]);
                    av[4] = ffma2(w2, v2.x, av[4]);
                    av[5] = ffma2(w2, v2.y, av[5]);
                    av[6] = ffma2(w2, v3.x, av[6]);
                    av[7] = ffma2(w2, v3.y, av[7]);
                }
            }
        }

        const float inv = 1.f / sum;
        const u64 inv2 = pk2(inv, inv);
        ulonglong2* og = (ulonglong2*)g_att4 + (size_t)(n * 4) * NPIX + pix;
        #pragma unroll
        for (int e = 0; e < 4; e++) {
            ulonglong2 o;
            o.x = fmul2(av[2 * e], inv2);
            o.y = fmul2(av[2 * e + 1], inv2);
            og[e * NPIX] = o;
        }
    }

    global_barrier(1);

    // ------------------- Phase 3: proj (CTAs 0..143) -----------------------
    if (cta >= 144) return;
    {
        float* As = sm.p.As;
        float* Bs = sm.p.Bs;
        const int pix0 = cta * 64;
        const int tp = tid >> 4;
        const int tout = tid & 15;

        u64 acc2[4][4];
        #pragma unroll
        for (int pp = 0; pp < 4; pp++)
            #pragma unroll
            for (int q = 0; q < 4; q++) acc2[pp][q] = 0ull;

        for (int kt = 0; kt < 2; kt++) {
            __syncthreads();
            {
                int p = tid & 63, k4 = tid >> 6;
                #pragma unroll
                for (int r2 = 0; r2 < 4; r2++) {
                    int pl = k4 + 4 * r2;
                    float4 v = g_att4[(size_t)(kt * 16 + pl) * NPIX + pix0 + p];
                    As[(pl * 4 + 0) * 64 + p] = v.x;
                    As[(pl * 4 + 1) * 64 + p] = v.y;
                    As[(pl * 4 + 2) * 64 + p] = v.z;
                    As[(pl * 4 + 3) * 64 + p] = v.w;
                }
            }
            {
                int o = tid & 127, g = tid >> 7;
                const float4* src = (const float4*)pw + (size_t)o * 32 + kt * 16;
                #pragma unroll
                for (int r2 = 0; r2 < 8; r2++) {
                    int kk = g + 2 * r2;
                    float4 v = src[kk];
                    Bs[(kk * 4 + 0) * 128 + o] = v.x;
                    Bs[(kk * 4 + 1) * 128 + o] = v.y;
                    Bs[(kk * 4 + 2) * 128 + o] = v.z;
                    Bs[(kk * 4 + 3) * 128 + o] = v.w;
                }
            }
            __syncthreads();

            #pragma unroll 8
            for (int k = 0; k < 64; k++) {
                float4 a = ((const float4*)As)[k * 16 + tp];
                ulonglong2 b0 = ((const ulonglong2*)Bs)[k * 32 + tout * 2];
                ulonglong2 b1 = ((const ulonglong2*)Bs)[k * 32 + tout * 2 + 1];
                u64 ap[4];
                ap[0] = pk2(a.x, a.x);
                ap[1] = pk2(a.y, a.y);
                ap[2] = pk2(a.z, a.z);
                ap[3] = pk2(a.w, a.w);
                #pragma unroll
                for (int pp = 0; pp < 4; pp++) {
                    acc2[pp][0] = ffma2(ap[pp], b0.x, acc2[pp][0]);
                    acc2[pp][1] = ffma2(ap[pp], b0.y, acc2[pp][1]);
                    acc2[pp][2] = ffma2(ap[pp], b1.x, acc2[pp][2]);
                    acc2[pp][3] = ffma2(ap[pp], b1.y, acc2[pp][3]);
                }
            }
        }

        float acc[4][8];
        #pragma unroll
        for (int pp = 0; pp < 4; pp++)
            #pragma unroll
            for (int q = 0; q < 4; q++)
                upk2(acc2[pp][q], acc[pp][2 * q], acc[pp][2 * q + 1]);

        #pragma unroll
        for (int oo = 0; oo < 8; oo++) {
            int o = tout * 8 + oo;
            float bias = pb[o];
            float4 r = make_float4(acc[0][oo] + bias, acc[1][oo] + bias,
                                   acc[2][oo] + bias, acc[3][oo] + bias);
            *(float4*)(out + (size_t)o * NPIX + pix0 + tp * 4) = r;
        }
    }
}

// ---------------------------------------------------------------------------
extern "C" void kernel_launch(void* const* d_in, const int* in_sizes, int n_in,
                              void* d_out, int out_size) {
    const float* x      = (const float*)d_in[0];
    const float* qkv_w  = (const float*)d_in[1];
    const float* qkv_b  = (const float*)d_in[2];
    const float* proj_w = (const float*)d_in[3];
    const float* proj_b = (const float*)d_in[4];
    float* out = (float*)d_out;

    fused_kernel<<<288, 256>>>(x, qkv_w, qkv_b, proj_w, proj_b, out);
}

// round 14
// speedup vs baseline: 1.1150x; 1.1150x over previous
#include <cuda_runtime.h>

#define HH 96
#define WW 96
#define NPIX 9216
#define NHEADS 8
#define HD 16
#define HSUB 48
#define NKEY (HSUB*HSUB)

typedef unsigned long long u64;

// Planar scratch layouts (coalesced: plane-major, pixel-minor).
__device__ __align__(16) float4 g_q4[NHEADS * 4 * NPIX];
__device__ __align__(16) float4 g_k4[NHEADS * 4 * NKEY];
__device__ __align__(16) float4 g_v4[NHEADS * 4 * NKEY];
__device__ __align__(16) float4 g_att4[32 * NPIX];

// ---- f32x2 packed math helpers -------------------------------------------
__device__ __forceinline__ u64 pk2(float lo, float hi) {
    u64 r; asm("mov.b64 %0,{%1,%2};" : "=l"(r) : "f"(lo), "f"(hi)); return r;
}
__device__ __forceinline__ void upk2(u64 p, float& lo, float& hi) {
    asm("mov.b64 {%0,%1},%2;" : "=f"(lo), "=f"(hi) : "l"(p));
}
__device__ __forceinline__ u64 ffma2(u64 a, u64 b, u64 c) {
    u64 d; asm("fma.rn.f32x2 %0,%1,%2,%3;" : "=l"(d) : "l"(a), "l"(b), "l"(c)); return d;
}
__device__ __forceinline__ u64 fmul2(u64 a, u64 b) {
    u64 d; asm("mul.rn.f32x2 %0,%1,%2;" : "=l"(d) : "l"(a), "l"(b)); return d;
}

// ---------------------------------------------------------------------------
// Kernel 1: grouped 3x3 conv, DIRECT-LDG (round-12 version, measured 8.4us).
// ---------------------------------------------------------------------------
__global__ __launch_bounds__(256) void conv_direct_kernel(
        const float* __restrict__ x,
        const float* __restrict__ wq,
        const float* __restrict__ bq) {
    __shared__ float ws[36];
    __shared__ float bs[4];
    const int b = blockIdx.x;
    const int tid = threadIdx.x;

    if (b < 576) {
        const int plane = b / 18;
        const int idx = (b - plane * 18) * 256 + tid;
        const int pi = idx / 96, j = idx - pi * 96;
        const int i0 = 2 * pi;
        const int o0 = plane * 4;

        if (tid < 36) ws[tid] = wq[o0 * 9 + tid];
        if (tid < 4)  bs[tid] = bq[o0 + tid];
        __syncthreads();

        const int s   = 3 - (o0 % 3);
        const int ic0 = o0 / 3;
        const bool up = i0 > 0, dn = i0 < 94, lf = j > 0, rt = j < 95;
        const int base = i0 * 96 + j;

        float a0A[4], a0B[4], a1A[4], a1B[4];
        #pragma unroll
        for (int pass = 0; pass < 2; pass++) {
            const float* xp = x + (size_t)(ic0 + pass) * NPIX + base;
            float m0 = (up && lf) ? xp[-97] : 0.f;
            float m1 = up         ? xp[-96] : 0.f;
            float m2 = (up && rt) ? xp[-95] : 0.f;
            float r00 = lf ? xp[-1] : 0.f;
            float r01 =      xp[0];
            float r02 = rt ? xp[1]  : 0.f;
            float r10 = lf ? xp[95] : 0.f;
            float r11 =      xp[96];
            float r12 = rt ? xp[97] : 0.f;
            float r20 = (dn && lf) ? xp[191] : 0.f;
            float r21 = dn         ? xp[192] : 0.f;
            float r22 = (dn && rt) ? xp[193] : 0.f;
            float* acc0 = pass ? a0B : a0A;
            float* acc1 = pass ? a1B : a1A;
            #pragma unroll
            for (int e = 0; e < 4; e++) {
                const float* w = ws + e * 9;
                float a = bs[e], c = bs[e];
                a = fmaf(w[0], m0, a);  a = fmaf(w[1], m1, a);  a = fmaf(w[2], m2, a);
                a = fmaf(w[3], r00, a); a = fmaf(w[4], r01, a); a = fmaf(w[5], r02, a);
                a = fmaf(w[6], r10, a); a = fmaf(w[7], r11, a); a = fmaf(w[8], r12, a);
                c = fmaf(w[0], r00, c); c = fmaf(w[1], r01, c); c = fmaf(w[2], r02, c);
                c = fmaf(w[3], r10, c); c = fmaf(w[4], r11, c); c = fmaf(w[5], r12, c);
                c = fmaf(w[6], r20, c); c = fmaf(w[7], r21, c); c = fmaf(w[8], r22, c);
                acc0[e] = a;
                acc1[e] = c;
            }
        }
        float o0v[4], o1v[4];
        #pragma unroll
        for (int e = 0; e < 4; e++) {
            o0v[e] = ((e < s) ? a0A[e] : a0B[e]) * 0.25f;
            o1v[e] = ((e < s) ? a1A[e] : a1B[e]) * 0.25f;
        }
        float4* dst = g_q4 + (size_t)plane * NPIX + base;
        dst[0]  = make_float4(o0v[0], o0v[1], o0v[2], o0v[3]);
        dst[96] = make_float4(o1v[0], o1v[1], o1v[2], o1v[3]);
    } else {
        int b2 = b - 576;
        const bool isk = b2 < 288;
        if (!isk) b2 -= 288;
        const int plane = b2 / 9;
        const int key = (b2 - plane * 9) * 256 + tid;
        const int gr = key / 48, gc = key - gr * 48;
        const int i = gr * 2, j = gc * 2;
        const int o0 = (isk ? 128 : 256) + plane * 4;

        if (tid < 36) ws[tid] = wq[o0 * 9 + tid];
        if (tid < 4)  bs[tid] = bq[o0 + tid];
        __syncthreads();

        const int s   = 3 - (o0 % 3);
        const int ic0 = o0 / 3;
        const bool up = i > 0, dn = i < 95, lf = j > 0, rt = j < 95;
        const int base = i * 96 + j;

        float accA[4], accB[4];
        #pragma unroll
        for (int pass = 0; pass < 2; pass++) {
            const float* xp = x + (size_t)(ic0 + pass) * NPIX + base;
            float v0 = (up && lf) ? xp[-97] : 0.f;
            float v1 = up         ? xp[-96] : 0.f;
            float v2 = (up && rt) ? xp[-95] : 0.f;
            float v3 = lf         ? xp[-1]  : 0.f;
            float v4 =              xp[0];
            float v5 = rt         ? xp[1]   : 0.f;
            float v6 = (dn && lf) ? xp[95]  : 0.f;
            float v7 = dn         ? xp[96]  : 0.f;
            float v8 = (dn && rt) ? xp[97]  : 0.f;
            float* acc = pass ? accB : accA;
            #pragma unroll
            for (int e = 0; e < 4; e++) {
                const float* w = ws + e * 9;
                float a = bs[e];
                a = fmaf(w[0], v0, a); a = fmaf(w[1], v1, a); a = fmaf(w[2], v2, a);
                a = fmaf(w[3], v3, a); a = fmaf(w[4], v4, a); a = fmaf(w[5], v5, a);
                a = fmaf(w[6], v6, a); a = fmaf(w[7], v7, a); a = fmaf(w[8], v8, a);
                acc[e] = a;
            }
        }
        float out[4];
        #pragma unroll
        for (int e = 0; e < 4; e++)
            out[e] = (e < s) ? accA[e] : accB[e];
        float4* dst = (isk ? g_k4 : g_v4) + (size_t)plane * NKEY + key;
        *dst = make_float4(out[0], out[1], out[2], out[3]);
    }
}

// ---------------------------------------------------------------------------
// Kernel 2: neighborhood attention, vertical query pairs at 256 threads.
// CTA = 16 rows x 32 cols of queries (512 queries), grid (3,6,8) = 144 CTAs.
// One thread = query rows (2a, 2a+1) at one column -> identical key window,
// so every K/V LDS.128 serves two queries: per-query crossbar traffic halves.
// Key tile 16 x 24 on the 48x48 grid, 80B stride (<=2 chunks per 128B bank
// granule per warp access -> stays at the 4-cycle LDS.128 floor).
// Dynamic SMEM: 2 * 384 keys * 80B = 61440B.
// ---------------------------------------------------------------------------
#define KROWS 16
#define KCOLS 24
#define KTOT  (KROWS * KCOLS)

__global__ __launch_bounds__(256) void attn_kernel() {
    extern __shared__ u64 smem_dyn[];
    u64* Kt = smem_dyn;               // KTOT * 10 u64
    u64* Vt = smem_dyn + KTOT * 10;
    const int tj = blockIdx.x, ti = blockIdx.y, n = blockIdx.z;
    const int tid = threadIdx.x;

    const int si0 = min(max(ti * 8 - 3, 0), 40);
    const int sj0 = max(tj * 16 - 3, 0);    // tj in 0..2; max start is 29 < 40

    // Load 16x24 key/value tile (384 keys, 1.5 per thread).
    for (int idx = tid; idx < KTOT; idx += 256) {
        int kr = idx / KCOLS, kc = idx - kr * KCOLS;
        int gr = min(si0 + kr, 47);
        int gc = min(sj0 + kc, 47);
        const int key = gr * HSUB + gc;
        const ulonglong2* kg = (const ulonglong2*)g_k4 + (size_t)(n * 4) * NKEY + key;
        const ulonglong2* vg = (const ulonglong2*)g_v4 + (size_t)(n * 4) * NKEY + key;
        #pragma unroll
        for (int e = 0; e < 4; e++) {
            ulonglong2 a = kg[e * NKEY];
            Kt[idx * 10 + 2 * e]     = a.x;
            Kt[idx * 10 + 2 * e + 1] = a.y;
            ulonglong2 b = vg[e * NKEY];
            Vt[idx * 10 + 2 * e]     = b.x;
            Vt[idx * 10 + 2 * e + 1] = b.y;
        }
    }
    __syncthreads();

    const int col = tid & 31;            // query column within tile
    const int rp  = tid >> 5;            // row pair 0..7
    const int qi0 = ti * 16 + 2 * rp;
    const int qj  = tj * 32 + col;
    const int pix0 = qi0 * 96 + qj;      // odd-row pixel = pix0 + 96
    const int reli = min(max(ti * 8 + rp - 3, 0), 40) - si0;
    const int relj = min(max((qj >> 1) - 3, 0), 40) - sj0;

    u64 qp0[8], qp1[8];
    {
        const ulonglong2* qg = (const ulonglong2*)g_q4 + (size_t)(n * 4) * NPIX + pix0;
        #pragma unroll
        for (int e = 0; e < 4; e++) {
            ulonglong2 a = qg[e * NPIX];
            qp0[2 * e] = a.x; qp0[2 * e + 1] = a.y;
            ulonglong2 b = qg[e * NPIX + 96];
            qp1[2 * e] = b.x; qp1[2 * e + 1] = b.y;
        }
    }

    float mx0 = -3.4e38f, mx1 = -3.4e38f;
    float sum0 = 0.f, sum1 = 0.f;
    u64 av0[8], av1[8];
    #pragma unroll
    for (int e = 0; e < 8; e++) { av0[e] = 0ull; av1[e] = 0ull; }

    #pragma unroll
    for (int wr = 0; wr < 8; wr++) {            // one window row per chunk
        const int rb = (reli + wr) * KCOLS + relj;
        float lg0[8], lg1[8];
        float cmx0 = -3.4e38f, cmx1 = -3.4e38f;
        #pragma unroll
        for (int wc = 0; wc < 8; wc++) {
            const ulonglong2* kp = (const ulonglong2*)&Kt[(rb + wc) * 10];
            ulonglong2 k0 = kp[0], k1 = kp[1], k2 = kp[2], k3 = kp[3];
            u64 a0 = fmul2(qp0[0], k0.x);
            u64 a1 = fmul2(qp1[0], k0.x);
            a0 = ffma2(qp0[1], k0.y, a0);  a1 = ffma2(qp1[1], k0.y, a1);
            a0 = ffma2(qp0[2], k1.x, a0);  a1 = ffma2(qp1[2], k1.x, a1);
            a0 = ffma2(qp0[3], k1.y, a0);  a1 = ffma2(qp1[3], k1.y, a1);
            a0 = ffma2(qp0[4], k2.x, a0);  a1 = ffma2(qp1[4], k2.x, a1);
            a0 = ffma2(qp0[5], k2.y, a0);  a1 = ffma2(qp1[5], k2.y, a1);
            a0 = ffma2(qp0[6], k3.x, a0);  a1 = ffma2(qp1[6], k3.x, a1);
            a0 = ffma2(qp0[7], k3.y, a0);  a1 = ffma2(qp1[7], k3.y, a1);
            float lo, hi;
            upk2(a0, lo, hi);
            float s0 = lo + hi;
            upk2(a1, lo, hi);
            float s1 = lo + hi;
            lg0[wc] = s0;  cmx0 = fmaxf(cmx0, s0);
            lg1[wc] = s1;  cmx1 = fmaxf(cmx1, s1);
        }
        const float nmx0 = fmaxf(mx0, cmx0);
        const float nmx1 = fmaxf(mx1, cmx1);
        const float r0 = __expf(mx0 - nmx0);
        const float r1 = __expf(mx1 - nmx1);
        sum0 *= r0;  sum1 *= r1;
        const u64 r02 = pk2(r0, r0), r12 = pk2(r1, r1);
        #pragma unroll
        for (int e = 0; e < 8; e++) {
            av0[e] = fmul2(av0[e], r02);
            av1[e] = fmul2(av1[e], r12);
        }
        mx0 = nmx0;  mx1 = nmx1;

        #pragma unroll
        for (int k = 0; k < 8; k++) {
            float e0 = __expf(lg0[k] - nmx0);
            float e1 = __expf(lg1[k] - nmx1);
            lg0[k] = e0;  sum0 += e0;
            lg1[k] = e1;  sum1 += e1;
        }

        #pragma unroll
        for (int wc = 0; wc < 8; wc++) {
            const u64 w0 = pk2(lg0[wc], lg0[wc]);
            const u64 w1 = pk2(lg1[wc], lg1[wc]);
            const ulonglong2* vp = (const ulonglong2*)&Vt[(rb + wc) * 10];
            ulonglong2 v0 = vp[0], v1 = vp[1], v2 = vp[2], v3 = vp[3];
            av0[0] = ffma2(w0, v0.x, av0[0]);  av1[0] = ffma2(w1, v0.x, av1[0]);
            av0[1] = ffma2(w0, v0.y, av0[1]);  av1[1] = ffma2(w1, v0.y, av1[1]);
            av0[2] = ffma2(w0, v1.x, av0[2]);  av1[2] = ffma2(w1, v1.x, av1[2]);
            av0[3] = ffma2(w0, v1.y, av0[3]);  av1[3] = ffma2(w1, v1.y, av1[3]);
            av0[4] = ffma2(w0, v2.x, av0[4]);  av1[4] = ffma2(w1, v2.x, av1[4]);
            av0[5] = ffma2(w0, v2.y, av0[5]);  av1[5] = ffma2(w1, v2.y, av1[5]);
            av0[6] = ffma2(w0, v3.x, av0[6]);  av1[6] = ffma2(w1, v3.x, av1[6]);
            av0[7] = ffma2(w0, v3.y, av0[7]);  av1[7] = ffma2(w1, v3.y, av1[7]);
        }
    }

    const float i0 = 1.f / sum0, i1 = 1.f / sum1;
    const u64 i02 = pk2(i0, i0), i12 = pk2(i1, i1);
    ulonglong2* og = (ulonglong2*)g_att4 + (size_t)(n * 4) * NPIX + pix0;
    #pragma unroll
    for (int e = 0; e < 4; e++) {
        ulonglong2 o0, o1;
        o0.x = fmul2(av0[2 * e], i02);
        o0.y = fmul2(av0[2 * e + 1], i02);
        o1.x = fmul2(av1[2 * e], i12);
        o1.y = fmul2(av1[2 * e + 1], i12);
        og[e * NPIX] = o0;
        og[e * NPIX + 96] = o1;
    }
}

// ---------------------------------------------------------------------------
// Kernel 3: 1x1 projection GEMM (round-12 version, unchanged).
// ---------------------------------------------------------------------------
__global__ __launch_bounds__(256) void proj_kernel(
        const float* __restrict__ pw,
        const float* __restrict__ pb,
        float* __restrict__ out) {
    __shared__ __align__(16) float As[64 * 64];
    __shared__ __align__(16) float Bs[64 * 128];
    const int pix0 = blockIdx.x * 64;
    const int tid = threadIdx.x;
    const int tp = tid >> 4;
    const int tout = tid & 15;

    u64 acc2[4][4];
    #pragma unroll
    for (int pp = 0; pp < 4; pp++)
        #pragma unroll
        for (int q = 0; q < 4; q++) acc2[pp][q] = 0ull;

    for (int kt = 0; kt < 2; kt++) {
        __syncthreads();
        {
            int p = tid & 63, k4 = tid >> 6;
            #pragma unroll
            for (int r2 = 0; r2 < 4; r2++) {
                int pl = k4 + 4 * r2;
                float4 v = g_att4[(size_t)(kt * 16 + pl) * NPIX + pix0 + p];
                As[(pl * 4 + 0) * 64 + p] = v.x;
                As[(pl * 4 + 1) * 64 + p] = v.y;
                As[(pl * 4 + 2) * 64 + p] = v.z;
                As[(pl * 4 + 3) * 64 + p] = v.w;
            }
        }
        {
            int o = tid & 127, g = tid >> 7;
            const float4* src = (const float4*)pw + (size_t)o * 32 + kt * 16;
            #pragma unroll
            for (int r2 = 0; r2 < 8; r2++) {
                int kk = g + 2 * r2;
                float4 v = src[kk];
                Bs[(kk * 4 + 0) * 128 + o] = v.x;
                Bs[(kk * 4 + 1) * 128 + o] = v.y;
                Bs[(kk * 4 + 2) * 128 + o] = v.z;
                Bs[(kk * 4 + 3) * 128 + o] = v.w;
            }
        }
        __syncthreads();

        #pragma unroll 8
        for (int k = 0; k < 64; k++) {
            float4 a = ((const float4*)As)[k * 16 + tp];
            ulonglong2 b0 = ((const ulonglong2*)Bs)[k * 32 + tout * 2];
            ulonglong2 b1 = ((const ulonglong2*)Bs)[k * 32 + tout * 2 + 1];
            u64 ap[4];
            ap[0] = pk2(a.x, a.x);
            ap[1] = pk2(a.y, a.y);
            ap[2] = pk2(a.z, a.z);
            ap[3] = pk2(a.w, a.w);
            #pragma unroll
            for (int pp = 0; pp < 4; pp++) {
                acc2[pp][0] = ffma2(ap[pp], b0.x, acc2[pp][0]);
                acc2[pp][1] = ffma2(ap[pp], b0.y, acc2[pp][1]);
                acc2[pp][2] = ffma2(ap[pp], b1.x, acc2[pp][2]);
                acc2[pp][3] = ffma2(ap[pp], b1.y, acc2[pp][3]);
            }
        }
    }

    float acc[4][8];
    #pragma unroll
    for (int pp = 0; pp < 4; pp++)
        #pragma unroll
        for (int q = 0; q < 4; q++)
            upk2(acc2[pp][q], acc[pp][2 * q], acc[pp][2 * q + 1]);

    #pragma unroll
    for (int oo = 0; oo < 8; oo++) {
        int o = tout * 8 + oo;
        float bias = pb[o];
        float4 r = make_float4(acc[0][oo] + bias, acc[1][oo] + bias,
                               acc[2][oo] + bias, acc[3][oo] + bias);
        *(float4*)(out + (size_t)o * NPIX + pix0 + tp * 4) = r;
    }
}

// ---------------------------------------------------------------------------
extern "C" void kernel_launch(void* const* d_in, const int* in_sizes, int n_in,
                              void* d_out, int out_size) {
    const float* x      = (const float*)d_in[0];
    const float* qkv_w  = (const float*)d_in[1];
    const float* qkv_b  = (const float*)d_in[2];
    const float* proj_w = (const float*)d_in[3];
    const float* proj_b = (const float*)d_in[4];
    float* out = (float*)d_out;

    static bool attr_set = false;
    if (!attr_set) {
        cudaFuncSetAttribute(attn_kernel,
                             cudaFuncAttributeMaxDynamicSharedMemorySize, 61440);
        attr_set = true;
    }

    conv_direct_kernel<<<1152, 256>>>(x, qkv_w, qkv_b);
    attn_kernel<<<dim3(3, 6, NHEADS), 256, 61440>>>();
    proj_kernel<<<144, 256>>>(proj_w, proj_b, out);
}